// round 7
// baseline (speedup 1.0000x reference)
#include <cuda_runtime.h>
#include <cstdint>

#define N_NODES 100000
#define N_EDGES 1600000
#define FEATS   128
#define N_CLASSES 16
#define NSCAN   98          // ceil(N_NODES / 1024)

// ---------------- static device scratch (no allocs allowed) ----------------
__device__ int      g_src[N_EDGES];
__device__ int      g_dst[N_EDGES];
__device__ int      g_rank[N_EDGES];       // rank of edge within its dst bucket
__device__ int      g_ssrc[N_EDGES];       // src*FEATS sorted by dst (CSR)
__device__ int      g_cnt[N_NODES];        // in-degree (self-cleaning)
__device__ int      g_row[N_NODES + 1];
__device__ unsigned g_status[NSCAN];       // lookback status (self-cleaning)
__device__ float    g_inv[N_NODES];
__device__ uint32_t g_wt[3 * FEATS * FEATS];  // W0..W2 pre-converted to tf32
__device__ float    g_bufA[(size_t)N_NODES * FEATS];  // activation ping
__device__ float    g_bufB[(size_t)N_NODES * FEATS];  // activation pong

// ---------------- tf32 / cp.async helpers ----------------------------------
__device__ __forceinline__ uint32_t f2tf32(float f) {
    uint32_t u;
    asm("cvt.rna.tf32.f32 %0, %1;" : "=r"(u) : "f"(f));
    return u;
}

__device__ __forceinline__ void mma_tf32(float4& d, const uint32_t a[4], const uint32_t b[2]) {
    asm volatile(
        "mma.sync.aligned.m16n8k8.row.col.f32.tf32.tf32.f32 "
        "{%0,%1,%2,%3},{%4,%5,%6,%7},{%8,%9},{%0,%1,%2,%3};"
        : "+f"(d.x), "+f"(d.y), "+f"(d.z), "+f"(d.w)
        : "r"(a[0]), "r"(a[1]), "r"(a[2]), "r"(a[3]), "r"(b[0]), "r"(b[1]));
}

__device__ __forceinline__ void cp16(void* smem_dst, const void* gsrc) {
    uint32_t a = (uint32_t)__cvta_generic_to_shared(smem_dst);
    asm volatile("cp.async.cg.shared.global [%0], [%1], 16;\n" :: "r"(a), "l"(gsrc));
}
__device__ __forceinline__ void cp_commit() {
    asm volatile("cp.async.commit_group;\n" ::);
}
template <int N>
__device__ __forceinline__ void cp_wait() {
    asm volatile("cp.async.wait_group %0;\n" :: "n"(N));
}

// ---- count + convert + rank, fused int64 detection + weight tf32 convert ---
__global__ void count_convert_kernel(const void* srcv, const void* dstv,
                                     const float* __restrict__ W0,
                                     const float* __restrict__ W1,
                                     const float* __restrict__ W2,
                                     int* __restrict__ s32, int* __restrict__ d32,
                                     int* __restrict__ rank, int* __restrict__ cnt,
                                     uint32_t* __restrict__ wt) {
    __shared__ int s_not64;
    const int lt = threadIdx.x;
    if (lt == 0) s_not64 = 0;
    __syncthreads();
    if (lt < 64) {
        int a = ((const int*)srcv)[2 * lt + 1];
        int b = ((const int*)dstv)[2 * lt + 1];
        if ((a | b) != 0) atomicOr(&s_not64, 1);
    }
    __syncthreads();
    const bool is64 = (s_not64 == 0);

    int i = blockIdx.x * blockDim.x + lt;

    if (i < 3 * FEATS * FEATS) {
        const float* Wp = (i < FEATS * FEATS) ? W0
                        : (i < 2 * FEATS * FEATS) ? W1 : W2;
        wt[i] = f2tf32(Wp[i & (FEATS * FEATS - 1)]);
    }

    if (i >= N_EDGES) return;
    int s, d;
    if (is64) {
        s = (int)((const long long*)srcv)[i];
        d = (int)((const long long*)dstv)[i];
    } else {
        s = ((const int*)srcv)[i];
        d = ((const int*)dstv)[i];
    }
    s32[i] = s;
    d32[i] = d;
    rank[i] = atomicAdd(&cnt[d], 1);
}

// ---- single-pass scan with decoupled lookback ------------------------------
// status word: 0 = invalid, (1<<30)|agg = aggregate ready, (2<<30)|incl = prefix ready.
// Values <= N_EDGES < 2^30. status zeroed by scatter_kernel for the next replay.
__global__ void scan_kernel(int* __restrict__ cnt, int n,
                            unsigned* __restrict__ status,
                            int* __restrict__ row, float* __restrict__ inv) {
    __shared__ int sm[2][1024];
    __shared__ int sred[32];
    __shared__ int s_agg, s_base;
    const int b = blockIdx.x, t = threadIdx.x;
    const int i = b * 1024 + t;
    const int x = (i < n) ? cnt[i] : 0;

    // fast block aggregate, publish early
    {
        int v = x;
        #pragma unroll
        for (int o = 16; o; o >>= 1) v += __shfl_down_sync(0xffffffffu, v, o);
        if ((t & 31) == 0) sred[t >> 5] = v;
        __syncthreads();
        if (t < 32) {
            int w = sred[t];
            #pragma unroll
            for (int o = 16; o; o >>= 1) w += __shfl_down_sync(0xffffffffu, w, o);
            if (t == 0) {
                s_agg = w;
                unsigned val = (b == 0) ? ((2u << 30) | (unsigned)w)
                                        : ((1u << 30) | (unsigned)w);
                atomicExch(&status[b], val);
            }
        }
    }
    __syncthreads();

    // full block inclusive scan
    int pi = 0;
    sm[0][t] = x;
    __syncthreads();
    for (int o = 1; o < 1024; o <<= 1) {
        sm[1 - pi][t] = sm[pi][t] + ((t >= o) ? sm[pi][t - o] : 0);
        pi ^= 1;
        __syncthreads();
    }

    // warp 0: lookback for exclusive block prefix
    if (t < 32) {
        int base = 0;
        if (b > 0) {
            int j = b - 1;
            for (;;) {
                int idx = j - t;
                unsigned s = 0;
                if (idx >= 0) {
                    do { s = *(volatile unsigned*)&status[idx]; } while (s == 0);
                }
                unsigned pfx = __ballot_sync(0xffffffffu, (s >> 30) == 2u);
                if (pfx) {
                    int fl = __ffs(pfx) - 1;           // closest predecessor with prefix
                    int contrib = (t <= fl) ? (int)(s & 0x3FFFFFFFu) : 0;
                    #pragma unroll
                    for (int o = 16; o; o >>= 1) contrib += __shfl_down_sync(0xffffffffu, contrib, o);
                    base += __shfl_sync(0xffffffffu, contrib, 0);
                    break;
                } else {
                    int contrib = (idx >= 0) ? (int)(s & 0x3FFFFFFFu) : 0;
                    #pragma unroll
                    for (int o = 16; o; o >>= 1) contrib += __shfl_down_sync(0xffffffffu, contrib, o);
                    base += __shfl_sync(0xffffffffu, contrib, 0);
                    j -= 32;
                    if (j < 0) break;                  // unreachable: block 0 is PREFIX
                }
            }
            if (t == 0) atomicExch(&status[b], (2u << 30) | (unsigned)(base + s_agg));
        }
        if (t == 0) s_base = base;
    }
    __syncthreads();

    if (i < n) {
        int excl = sm[pi][t] - x + s_base;
        row[i] = excl;
        inv[i] = 1.0f / fmaxf((float)x, 1.0f);
        cnt[i] = 0;                       // self-clean for next replay
        if (i == n - 1) row[n] = excl + x;
    }
}

// ---------------- CSR scatter, atomic-free; also cleans scan status ---------
__global__ void scatter_kernel(const int* __restrict__ s32, const int* __restrict__ d32,
                               const int* __restrict__ rank, const int* __restrict__ row,
                               int* __restrict__ ssrc, unsigned* __restrict__ status) {
    int i = blockIdx.x * blockDim.x + threadIdx.x;
    if (i < NSCAN) status[i] = 0;         // reset lookback status for next replay
    if (i >= N_EDGES) return;
    int pos = row[d32[i]] + rank[i];
    ssrc[pos] = s32[i] * FEATS;
}

// ---------------- fused layer: z into smem, then TF32 GEMM ------------------
// IN and OUT must be DIFFERENT buffers (cross-block gather reads IN while
// other blocks write OUT). 256 threads. Phase 1: 8 warps aggregate 16 nodes
// each into As[128][132]. Phase 2: GEMM out = relu(As @ W + b).
#define ASF 132
#define WSF 132
#define FUSED_SMEM (128 * ASF * 4 + 2 * 32 * WSF * 4)   // 101376 B

template <bool RELU>
__global__ __launch_bounds__(256, 2)
void fused_kernel(const float* __restrict__ h,
                  const int* __restrict__ row, const int* __restrict__ ssrc,
                  const float* __restrict__ inv, const float* __restrict__ eps,
                  int layer, const uint32_t* __restrict__ Wt,
                  const float* __restrict__ bias, float* __restrict__ out, int M) {
    constexpr int K = 128, KB = 32, BM = 128, BN = 128;
    extern __shared__ char smem_raw[];
    float*    As = (float*)smem_raw;                        // [128][ASF]
    uint32_t* Ws = (uint32_t*)(smem_raw + BM * ASF * 4);    // [2][32][WSF]

    const int tid = threadIdx.x;
    const int wid = tid >> 5;
    const int lane = tid & 31;
    const int rb = blockIdx.x * BM;

    auto load_w = [&](int st, int kc) {
        #pragma unroll
        for (int idx = tid; idx < KB * (BN / 4); idx += 256) {
            int k = idx >> 5, n4 = (idx & 31) * 4;
            cp16(&Ws[(st * KB + k) * WSF + n4], Wt + (size_t)(kc + k) * BN + n4);
        }
    };
    load_w(0, 0);            // prefetch W chunk 0 while we aggregate
    cp_commit();

    // ---- phase 1: aggregation into As ----
    const float e1 = 1.0f + __ldg(eps + layer);
    const int fo = lane * 4;
    #pragma unroll 1
    for (int ii = 0; ii < 16; ++ii) {
        int r = wid * 16 + ii;
        int node = rb + r;
        float4 zv = make_float4(0.f, 0.f, 0.f, 0.f);
        if (node < M) {
            const int beg = __ldg(row + node);
            const int end = __ldg(row + node + 1);
            float ax = 0.f, ay = 0.f, az = 0.f, aw = 0.f;
            int e = beg;
            for (; e + 3 < end; e += 4) {
                int o0 = __ldg(ssrc + e);
                int o1 = __ldg(ssrc + e + 1);
                int o2 = __ldg(ssrc + e + 2);
                int o3 = __ldg(ssrc + e + 3);
                float4 v0 = *(const float4*)(h + (size_t)o0 + fo);
                float4 v1 = *(const float4*)(h + (size_t)o1 + fo);
                float4 v2 = *(const float4*)(h + (size_t)o2 + fo);
                float4 v3 = *(const float4*)(h + (size_t)o3 + fo);
                ax += (v0.x + v1.x) + (v2.x + v3.x);
                ay += (v0.y + v1.y) + (v2.y + v3.y);
                az += (v0.z + v1.z) + (v2.z + v3.z);
                aw += (v0.w + v1.w) + (v2.w + v3.w);
            }
            for (; e < end; ++e) {
                int o0 = __ldg(ssrc + e);
                float4 v0 = *(const float4*)(h + (size_t)o0 + fo);
                ax += v0.x; ay += v0.y; az += v0.z; aw += v0.w;
            }
            float sc = __ldg(inv + node);
            float4 hv = *(const float4*)(h + (size_t)node * FEATS + fo);
            zv.x = e1 * hv.x + sc * ax;
            zv.y = e1 * hv.y + sc * ay;
            zv.z = e1 * hv.z + sc * az;
            zv.w = e1 * hv.w + sc * aw;
        }
        *(float4*)&As[r * ASF + fo] = zv;
    }

    // ---- phase 2: GEMM ----
    const int g = lane >> 2, t = lane & 3;
    const int wm = wid >> 2, wn = wid & 3;

    float4 acc[4][4];
    #pragma unroll
    for (int i = 0; i < 4; ++i)
        #pragma unroll
        for (int j = 0; j < 4; ++j) acc[i][j] = make_float4(0.f, 0.f, 0.f, 0.f);

    #pragma unroll
    for (int kci = 0; kci < K / KB; ++kci) {
        if (kci < K / KB - 1) {
            load_w((kci + 1) & 1, (kci + 1) * KB);
            cp_commit();
            cp_wait<1>();
        } else {
            cp_wait<0>();
        }
        __syncthreads();   // covers As (first iter) + Ws chunk visibility
        const int st = kci & 1;

        #pragma unroll
        for (int ks = 0; ks < KB / 8; ++ks) {
            const int kb = kci * KB + ks * 8;   // column in As
            const int kw = ks * 8;              // row in Ws chunk
            uint32_t a[4][4], b[4][2];
            #pragma unroll
            for (int mt = 0; mt < 4; ++mt) {
                int r0 = wm * 64 + mt * 16 + g;
                a[mt][0] = f2tf32(As[r0 * ASF + kb + t]);
                a[mt][1] = f2tf32(As[(r0 + 8) * ASF + kb + t]);
                a[mt][2] = f2tf32(As[r0 * ASF + kb + t + 4]);
                a[mt][3] = f2tf32(As[(r0 + 8) * ASF + kb + t + 4]);
            }
            #pragma unroll
            for (int nt = 0; nt < 4; ++nt) {
                int c = wn * 32 + nt * 8 + g;
                b[nt][0] = Ws[(st * KB + kw + t) * WSF + c];
                b[nt][1] = Ws[(st * KB + kw + t + 4) * WSF + c];
            }
            #pragma unroll
            for (int mt = 0; mt < 4; ++mt)
                #pragma unroll
                for (int nt = 0; nt < 4; ++nt)
                    mma_tf32(acc[mt][nt], a[mt], b[nt]);
        }
        __syncthreads();
    }

    #pragma unroll
    for (int nt = 0; nt < 4; ++nt) {
        int c = wn * 32 + nt * 8 + 2 * t;
        float bx = __ldg(bias + c);
        float by = __ldg(bias + c + 1);
        #pragma unroll
        for (int mt = 0; mt < 4; ++mt) {
            int r0 = rb + wm * 64 + mt * 16 + g;
            float2 lo, hi;
            lo.x = acc[mt][nt].x + bx;
            lo.y = acc[mt][nt].y + by;
            hi.x = acc[mt][nt].z + bx;
            hi.y = acc[mt][nt].w + by;
            if (RELU) {
                lo.x = fmaxf(lo.x, 0.f); lo.y = fmaxf(lo.y, 0.f);
                hi.x = fmaxf(hi.x, 0.f); hi.y = fmaxf(hi.y, 0.f);
            }
            if (r0 < M)     *(float2*)(out + (size_t)r0 * BN + c) = lo;
            if (r0 + 8 < M) *(float2*)(out + (size_t)(r0 + 8) * BN + c) = hi;
        }
    }
}

// ---------------- layer-3 aggregation (z to gmem) ---------------------------
__global__ void aggz_kernel(const float* __restrict__ h,
                            const int* __restrict__ row, const int* __restrict__ ssrc,
                            const float* __restrict__ inv,
                            const float* __restrict__ eps, int layer,
                            float* __restrict__ z) {
    int gt = blockIdx.x * blockDim.x + threadIdx.x;
    int node = gt >> 5;
    if (node >= N_NODES) return;
    int lane = gt & 31;
    const int beg = __ldg(row + node);
    const int end = __ldg(row + node + 1);
    const int fo = lane * 4;

    float ax = 0.f, ay = 0.f, az = 0.f, aw = 0.f;
    int e = beg;
    for (; e + 3 < end; e += 4) {
        int o0 = __ldg(ssrc + e);
        int o1 = __ldg(ssrc + e + 1);
        int o2 = __ldg(ssrc + e + 2);
        int o3 = __ldg(ssrc + e + 3);
        float4 v0 = *(const float4*)(h + (size_t)o0 + fo);
        float4 v1 = *(const float4*)(h + (size_t)o1 + fo);
        float4 v2 = *(const float4*)(h + (size_t)o2 + fo);
        float4 v3 = *(const float4*)(h + (size_t)o3 + fo);
        ax += (v0.x + v1.x) + (v2.x + v3.x);
        ay += (v0.y + v1.y) + (v2.y + v3.y);
        az += (v0.z + v1.z) + (v2.z + v3.z);
        aw += (v0.w + v1.w) + (v2.w + v3.w);
    }
    for (; e < end; ++e) {
        int o0 = __ldg(ssrc + e);
        float4 v0 = *(const float4*)(h + (size_t)o0 + fo);
        ax += v0.x; ay += v0.y; az += v0.z; aw += v0.w;
    }

    float sc = __ldg(inv + node);
    float e1 = 1.0f + __ldg(eps + layer);
    float4 hv = *(const float4*)(h + (size_t)node * FEATS + fo);
    float4 zv;
    zv.x = e1 * hv.x + sc * ax;
    zv.y = e1 * hv.y + sc * ay;
    zv.z = e1 * hv.z + sc * az;
    zv.w = e1 * hv.w + sc * aw;
    *(float4*)(z + (size_t)node * FEATS + fo) = zv;
}

// ---------------- fp32 MLP for the 16-class head ---------------------------
template <int BM, int BN, int TM, int TN, bool RELU>
__global__ void mlp_kernel(const float* __restrict__ Z, const float* __restrict__ W,
                           const float* __restrict__ bias, float* __restrict__ out, int M) {
    constexpr int K = 128, KB = 32;
    constexpr int TX = BN / TN, TY = BM / TM, NT = TX * TY;
    __shared__ float As[BM][KB + 1];
    __shared__ float Ws[KB][BN];
    const int tid = threadIdx.x;
    const int tx = tid % TX, ty = tid / TX;
    const int rb = blockIdx.x * BM;

    float acc[TM][TN];
    #pragma unroll
    for (int i = 0; i < TM; ++i)
        #pragma unroll
        for (int j = 0; j < TN; ++j) acc[i][j] = 0.f;

    for (int kc = 0; kc < K; kc += KB) {
        #pragma unroll
        for (int idx = tid; idx < BM * (KB / 4); idx += NT) {
            int r = idx / (KB / 4);
            int f4 = idx % (KB / 4);
            float4 v = make_float4(0.f, 0.f, 0.f, 0.f);
            int gr = rb + r;
            if (gr < M) v = *(const float4*)(Z + (size_t)gr * K + kc + f4 * 4);
            As[r][f4 * 4 + 0] = v.x;
            As[r][f4 * 4 + 1] = v.y;
            As[r][f4 * 4 + 2] = v.z;
            As[r][f4 * 4 + 3] = v.w;
        }
        #pragma unroll
        for (int idx = tid; idx < KB * (BN / 4); idx += NT) {
            int kk = idx / (BN / 4);
            int c4 = idx % (BN / 4);
            *(float4*)&Ws[kk][c4 * 4] = *(const float4*)(W + (size_t)(kc + kk) * BN + c4 * 4);
        }
        __syncthreads();
        #pragma unroll
        for (int k = 0; k < KB; ++k) {
            float a[TM], bb[TN];
            #pragma unroll
            for (int i = 0; i < TM; ++i) a[i] = As[ty * TM + i][k];
            #pragma unroll
            for (int j = 0; j < TN; ++j) bb[j] = Ws[k][tx * TN + j];
            #pragma unroll
            for (int i = 0; i < TM; ++i)
                #pragma unroll
                for (int j = 0; j < TN; ++j)
                    acc[i][j] = fmaf(a[i], bb[j], acc[i][j]);
        }
        __syncthreads();
    }

    float bv[TN];
    #pragma unroll
    for (int j = 0; j < TN; ++j) bv[j] = __ldg(bias + tx * TN + j);
    #pragma unroll
    for (int i = 0; i < TM; ++i) {
        int gr = rb + ty * TM + i;
        if (gr < M) {
            #pragma unroll
            for (int j = 0; j < TN; ++j) {
                float o = acc[i][j] + bv[j];
                if (RELU) o = fmaxf(o, 0.f);
                out[(size_t)gr * BN + tx * TN + j] = o;
            }
        }
    }
}

// ---------------- host orchestration ----------------------------------------
extern "C" void kernel_launch(void* const* d_in, const int* in_sizes, int n_in,
                              void* d_out, int out_size) {
    (void)in_sizes; (void)n_in; (void)out_size;
    const float* feats = (const float*)d_in[0];
    const void*  srcv  = d_in[1];
    const void*  dstv  = d_in[2];
    const float* W0 = (const float*)d_in[3];
    const float* b0 = (const float*)d_in[4];
    const float* W1 = (const float*)d_in[5];
    const float* b1 = (const float*)d_in[6];
    const float* W2 = (const float*)d_in[7];
    const float* b2 = (const float*)d_in[8];
    const float* W3 = (const float*)d_in[9];
    const float* b3 = (const float*)d_in[10];
    const float* eps = (const float*)d_in[11];
    float* outp = (float*)d_out;

    void *p_src, *p_dst, *p_rank, *p_ssrc, *p_cnt, *p_row, *p_status, *p_inv, *p_wt, *p_a, *p_b;
    cudaGetSymbolAddress(&p_src, g_src);
    cudaGetSymbolAddress(&p_dst, g_dst);
    cudaGetSymbolAddress(&p_rank, g_rank);
    cudaGetSymbolAddress(&p_ssrc, g_ssrc);
    cudaGetSymbolAddress(&p_cnt, g_cnt);
    cudaGetSymbolAddress(&p_row, g_row);
    cudaGetSymbolAddress(&p_status, g_status);
    cudaGetSymbolAddress(&p_inv, g_inv);
    cudaGetSymbolAddress(&p_wt, g_wt);
    cudaGetSymbolAddress(&p_a, g_bufA);
    cudaGetSymbolAddress(&p_b, g_bufB);

    int* src32 = (int*)p_src;
    int* dst32 = (int*)p_dst;
    int* rankp = (int*)p_rank;
    int* ssrc  = (int*)p_ssrc;
    int* cnt   = (int*)p_cnt;
    int* rowp  = (int*)p_row;
    unsigned* statusp = (unsigned*)p_status;
    float* inv = (float*)p_inv;
    uint32_t* wt = (uint32_t*)p_wt;
    float* bufA = (float*)p_a;
    float* bufB = (float*)p_b;

    cudaFuncSetAttribute(fused_kernel<true>,
                         cudaFuncAttributeMaxDynamicSharedMemorySize, FUSED_SMEM);

    const int EB = 256;
    const int egrid = (N_EDGES + EB - 1) / EB;

    // ---- preprocessing: 3 launches ----
    count_convert_kernel<<<egrid, EB>>>(srcv, dstv, W0, W1, W2,
                                        src32, dst32, rankp, cnt, wt);
    scan_kernel<<<NSCAN, 1024>>>(cnt, N_NODES, statusp, rowp, inv);
    scatter_kernel<<<egrid, EB>>>(src32, dst32, rankp, rowp, ssrc, statusp);

    // ---- 4 GIN layers: fused agg+GEMM 0..2 with ping-pong buffers ---------
    // layer0: feats -> A;  layer1: A -> B;  layer2: B -> A;
    // layer3: aggz A -> B, head B -> out.  (in != out always: race-free)
    const int mgrid = (N_NODES + 127) / 128;

    fused_kernel<true><<<mgrid, 256, FUSED_SMEM>>>(feats, rowp, ssrc, inv, eps, 0,
                                                   wt, b0, bufA, N_NODES);
    fused_kernel<true><<<mgrid, 256, FUSED_SMEM>>>(bufA, rowp, ssrc, inv, eps, 1,
                                                   wt + FEATS * FEATS, b1, bufB, N_NODES);
    fused_kernel<true><<<mgrid, 256, FUSED_SMEM>>>(bufB, rowp, ssrc, inv, eps, 2,
                                                   wt + 2 * FEATS * FEATS, b2, bufA, N_NODES);

    const int agrid = ((size_t)N_NODES * 32 + 255) / 256;
    aggz_kernel<<<agrid, 256>>>(bufA, rowp, ssrc, inv, eps, 3, bufB);
    mlp_kernel<128, 16, 8, 2, false><<<mgrid, 128>>>(bufB, W3, b3, outp, N_NODES);
}

// round 9
// speedup vs baseline: 1.5022x; 1.5022x over previous
#include <cuda_runtime.h>
#include <cstdint>

#define N_NODES 100000
#define N_EDGES 1600000
#define FEATS   128
#define N_CLASSES 16
#define NSCAN   98          // ceil(N_NODES / 1024)

// ---------------- static device scratch (no allocs allowed) ----------------
__device__ int      g_src[N_EDGES];
__device__ int      g_dst[N_EDGES];
__device__ int      g_rank[N_EDGES];       // rank of edge within its dst bucket
__device__ int      g_ssrc[N_EDGES];       // src*FEATS sorted by dst (CSR)
__device__ int      g_cnt[N_NODES];        // in-degree (self-cleaning)
__device__ int      g_row[N_NODES + 1];
__device__ unsigned g_status[NSCAN];       // lookback status (self-cleaning)
__device__ float    g_inv[N_NODES];
__device__ uint32_t g_wt[3 * FEATS * FEATS];  // W0..W2 pre-converted to tf32
__device__ float    g_z[(size_t)(N_NODES + 128) * FEATS];  // +128 pad rows
__device__ float    g_h[(size_t)N_NODES * FEATS];

// ---------------- helpers ---------------------------------------------------
__device__ __forceinline__ uint32_t f2tf32(float f) {
    uint32_t u;
    asm("cvt.rna.tf32.f32 %0, %1;" : "=r"(u) : "f"(f));
    return u;
}

__device__ __forceinline__ void mma_tf32(float4& d, const uint32_t a[4], const uint32_t b[2]) {
    asm volatile(
        "mma.sync.aligned.m16n8k8.row.col.f32.tf32.tf32.f32 "
        "{%0,%1,%2,%3},{%4,%5,%6,%7},{%8,%9},{%0,%1,%2,%3};"
        : "+f"(d.x), "+f"(d.y), "+f"(d.z), "+f"(d.w)
        : "r"(a[0]), "r"(a[1]), "r"(a[2]), "r"(a[3]), "r"(b[0]), "r"(b[1]));
}

// L1-bypassing 16B gather load (streamy random access: cache in L2 only)
__device__ __forceinline__ float4 ldcg4(const float* p) {
    float4 v;
    asm("ld.global.cg.v4.f32 {%0,%1,%2,%3}, [%4];"
        : "=f"(v.x), "=f"(v.y), "=f"(v.z), "=f"(v.w) : "l"(p));
    return v;
}

__device__ __forceinline__ void cp16(void* smem_dst, const void* gsrc) {
    uint32_t a = (uint32_t)__cvta_generic_to_shared(smem_dst);
    asm volatile("cp.async.cg.shared.global [%0], [%1], 16;\n" :: "r"(a), "l"(gsrc));
}
__device__ __forceinline__ void cp_commit() {
    asm volatile("cp.async.commit_group;\n" ::);
}
template <int N>
__device__ __forceinline__ void cp_wait() {
    asm volatile("cp.async.wait_group %0;\n" :: "n"(N));
}

// ---- count + convert + rank, fused int64 detection + weight tf32 convert ---
__global__ void count_convert_kernel(const void* srcv, const void* dstv,
                                     const float* __restrict__ W0,
                                     const float* __restrict__ W1,
                                     const float* __restrict__ W2,
                                     int* __restrict__ s32, int* __restrict__ d32,
                                     int* __restrict__ rank, int* __restrict__ cnt,
                                     uint32_t* __restrict__ wt) {
    __shared__ int s_not64;
    const int lt = threadIdx.x;
    if (lt == 0) s_not64 = 0;
    __syncthreads();
    if (lt < 64) {
        int a = ((const int*)srcv)[2 * lt + 1];
        int b = ((const int*)dstv)[2 * lt + 1];
        if ((a | b) != 0) atomicOr(&s_not64, 1);
    }
    __syncthreads();
    const bool is64 = (s_not64 == 0);

    int i = blockIdx.x * blockDim.x + lt;

    if (i < 3 * FEATS * FEATS) {
        const float* Wp = (i < FEATS * FEATS) ? W0
                        : (i < 2 * FEATS * FEATS) ? W1 : W2;
        wt[i] = f2tf32(Wp[i & (FEATS * FEATS - 1)]);
    }

    if (i >= N_EDGES) return;
    int s, d;
    if (is64) {
        s = (int)((const long long*)srcv)[i];
        d = (int)((const long long*)dstv)[i];
    } else {
        s = ((const int*)srcv)[i];
        d = ((const int*)dstv)[i];
    }
    s32[i] = s;
    d32[i] = d;
    rank[i] = atomicAdd(&cnt[d], 1);
}

// ---- single-pass scan with decoupled lookback ------------------------------
// status: 0 = invalid, (1<<30)|agg = aggregate ready, (2<<30)|incl = prefix ready.
// Values <= N_EDGES < 2^30. status zeroed by scatter_kernel for the next replay.
__global__ void scan_kernel(int* __restrict__ cnt, int n,
                            unsigned* __restrict__ status,
                            int* __restrict__ row, float* __restrict__ inv) {
    __shared__ int sm[2][1024];
    __shared__ int sred[32];
    __shared__ int s_agg, s_base;
    const int b = blockIdx.x, t = threadIdx.x;
    const int i = b * 1024 + t;
    const int x = (i < n) ? cnt[i] : 0;

    {
        int v = x;
        #pragma unroll
        for (int o = 16; o; o >>= 1) v += __shfl_down_sync(0xffffffffu, v, o);
        if ((t & 31) == 0) sred[t >> 5] = v;
        __syncthreads();
        if (t < 32) {
            int w = sred[t];
            #pragma unroll
            for (int o = 16; o; o >>= 1) w += __shfl_down_sync(0xffffffffu, w, o);
            if (t == 0) {
                s_agg = w;
                unsigned val = (b == 0) ? ((2u << 30) | (unsigned)w)
                                        : ((1u << 30) | (unsigned)w);
                atomicExch(&status[b], val);
            }
        }
    }
    __syncthreads();

    int pi = 0;
    sm[0][t] = x;
    __syncthreads();
    for (int o = 1; o < 1024; o <<= 1) {
        sm[1 - pi][t] = sm[pi][t] + ((t >= o) ? sm[pi][t - o] : 0);
        pi ^= 1;
        __syncthreads();
    }

    if (t < 32) {
        int base = 0;
        if (b > 0) {
            int j = b - 1;
            for (;;) {
                int idx = j - t;
                unsigned s = 0;
                if (idx >= 0) {
                    do { s = *(volatile unsigned*)&status[idx]; } while (s == 0);
                }
                unsigned pfx = __ballot_sync(0xffffffffu, (s >> 30) == 2u);
                if (pfx) {
                    int fl = __ffs(pfx) - 1;
                    int contrib = (t <= fl) ? (int)(s & 0x3FFFFFFFu) : 0;
                    #pragma unroll
                    for (int o = 16; o; o >>= 1) contrib += __shfl_down_sync(0xffffffffu, contrib, o);
                    base += __shfl_sync(0xffffffffu, contrib, 0);
                    break;
                } else {
                    int contrib = (idx >= 0) ? (int)(s & 0x3FFFFFFFu) : 0;
                    #pragma unroll
                    for (int o = 16; o; o >>= 1) contrib += __shfl_down_sync(0xffffffffu, contrib, o);
                    base += __shfl_sync(0xffffffffu, contrib, 0);
                    j -= 32;
                    if (j < 0) break;
                }
            }
            if (t == 0) atomicExch(&status[b], (2u << 30) | (unsigned)(base + s_agg));
        }
        if (t == 0) s_base = base;
    }
    __syncthreads();

    if (i < n) {
        int excl = sm[pi][t] - x + s_base;
        row[i] = excl;
        inv[i] = 1.0f / fmaxf((float)x, 1.0f);
        cnt[i] = 0;                       // self-clean for next replay
        if (i == n - 1) row[n] = excl + x;
    }
}

// ---------------- CSR scatter, atomic-free; also cleans scan status ---------
__global__ void scatter_kernel(const int* __restrict__ s32, const int* __restrict__ d32,
                               const int* __restrict__ rank, const int* __restrict__ row,
                               int* __restrict__ ssrc, unsigned* __restrict__ status) {
    int i = blockIdx.x * blockDim.x + threadIdx.x;
    if (i < NSCAN) status[i] = 0;
    if (i >= N_EDGES) return;
    int pos = row[d32[i]] + rank[i];
    ssrc[pos] = s32[i] * FEATS;
}

// ---------------- aggregation: z = (1+eps)*h + inv_deg * sum_nbr ------------
// One warp per node, lane L handles features [4L, 4L+4). Gathers bypass L1.
__global__ void aggz_kernel(const float* __restrict__ h,
                            const int* __restrict__ row, const int* __restrict__ ssrc,
                            const float* __restrict__ inv,
                            const float* __restrict__ eps, int layer,
                            float* __restrict__ z) {
    int gt = blockIdx.x * blockDim.x + threadIdx.x;
    int node = gt >> 5;
    if (node >= N_NODES) return;
    int lane = gt & 31;
    const int beg = __ldg(row + node);
    const int end = __ldg(row + node + 1);
    const int fo = lane * 4;

    float ax = 0.f, ay = 0.f, az = 0.f, aw = 0.f;
    int e = beg;
    for (; e + 3 < end; e += 4) {
        int o0 = __ldg(ssrc + e);
        int o1 = __ldg(ssrc + e + 1);
        int o2 = __ldg(ssrc + e + 2);
        int o3 = __ldg(ssrc + e + 3);
        float4 v0 = ldcg4(h + (size_t)o0 + fo);
        float4 v1 = ldcg4(h + (size_t)o1 + fo);
        float4 v2 = ldcg4(h + (size_t)o2 + fo);
        float4 v3 = ldcg4(h + (size_t)o3 + fo);
        ax += (v0.x + v1.x) + (v2.x + v3.x);
        ay += (v0.y + v1.y) + (v2.y + v3.y);
        az += (v0.z + v1.z) + (v2.z + v3.z);
        aw += (v0.w + v1.w) + (v2.w + v3.w);
    }
    for (; e < end; ++e) {
        int o0 = __ldg(ssrc + e);
        float4 v0 = ldcg4(h + (size_t)o0 + fo);
        ax += v0.x; ay += v0.y; az += v0.z; aw += v0.w;
    }

    float sc = __ldg(inv + node);
    float e1 = 1.0f + __ldg(eps + layer);
    float4 hv = ldcg4(h + (size_t)node * FEATS + fo);
    float4 zv;
    zv.x = e1 * hv.x + sc * ax;
    zv.y = e1 * hv.y + sc * ay;
    zv.z = e1 * hv.z + sc * az;
    zv.w = e1 * hv.w + sc * aw;
    *(float4*)(z + (size_t)node * FEATS + fo) = zv;
}

// ------- TF32 MLP, cp.async double-buffered: out = relu(Z @ W + b) ----------
#define AS_STRIDE 36
#define WS_STRIDE 132
#define MMA_SMEM_BYTES (2 * 128 * AS_STRIDE * 4 + 2 * 32 * WS_STRIDE * 4)

template <bool RELU>
__global__ __launch_bounds__(256, 2)
void mma_mlp_kernel(const float* __restrict__ Z, const uint32_t* __restrict__ Wt,
                    const float* __restrict__ bias, float* __restrict__ out, int M) {
    constexpr int K = 128, KB = 32, BM = 128, BN = 128;
    extern __shared__ char smem_raw[];
    float*    As = (float*)smem_raw;                                 // [2][128][36]
    uint32_t* Ws = (uint32_t*)(smem_raw + 2 * BM * AS_STRIDE * 4);   // [2][32][132]

    const int tid = threadIdx.x;
    const int wid = tid >> 5;
    const int lane = tid & 31;
    const int g = lane >> 2;
    const int t = lane & 3;
    const int wm = wid >> 2;
    const int wn = wid & 3;
    const int rb = blockIdx.x * BM;

    auto load_tiles = [&](int st, int kc) {
        #pragma unroll
        for (int idx = tid; idx < BM * (KB / 4); idx += 256) {
            int r = idx >> 3, c4 = (idx & 7) * 4;
            cp16(&As[(st * BM + r) * AS_STRIDE + c4],
                 Z + (size_t)(rb + r) * K + kc + c4);
        }
        #pragma unroll
        for (int idx = tid; idx < KB * (BN / 4); idx += 256) {
            int k = idx >> 5, n4 = (idx & 31) * 4;
            cp16(&Ws[(st * KB + k) * WS_STRIDE + n4],
                 Wt + (size_t)(kc + k) * BN + n4);
        }
    };

    float4 acc[4][4];
    #pragma unroll
    for (int i = 0; i < 4; ++i)
        #pragma unroll
        for (int j = 0; j < 4; ++j) acc[i][j] = make_float4(0.f, 0.f, 0.f, 0.f);

    load_tiles(0, 0);
    cp_commit();

    #pragma unroll
    for (int kci = 0; kci < K / KB; ++kci) {
        if (kci < K / KB - 1) {
            load_tiles((kci + 1) & 1, (kci + 1) * KB);
            cp_commit();
            cp_wait<1>();
        } else {
            cp_wait<0>();
        }
        __syncthreads();
        const int st = kci & 1;

        #pragma unroll
        for (int ks = 0; ks < KB / 8; ++ks) {
            const int kb = ks * 8;
            uint32_t a[4][4], b[4][2];
            #pragma unroll
            for (int mt = 0; mt < 4; ++mt) {
                int r0 = wm * 64 + mt * 16 + g;
                a[mt][0] = f2tf32(As[(st * BM + r0) * AS_STRIDE + kb + t]);
                a[mt][1] = f2tf32(As[(st * BM + r0 + 8) * AS_STRIDE + kb + t]);
                a[mt][2] = f2tf32(As[(st * BM + r0) * AS_STRIDE + kb + t + 4]);
                a[mt][3] = f2tf32(As[(st * BM + r0 + 8) * AS_STRIDE + kb + t + 4]);
            }
            #pragma unroll
            for (int nt = 0; nt < 4; ++nt) {
                int c = wn * 32 + nt * 8 + g;
                b[nt][0] = Ws[(st * KB + kb + t) * WS_STRIDE + c];
                b[nt][1] = Ws[(st * KB + kb + t + 4) * WS_STRIDE + c];
            }
            #pragma unroll
            for (int mt = 0; mt < 4; ++mt)
                #pragma unroll
                for (int nt = 0; nt < 4; ++nt)
                    mma_tf32(acc[mt][nt], a[mt], b[nt]);
        }
        __syncthreads();
    }

    #pragma unroll
    for (int nt = 0; nt < 4; ++nt) {
        int c = wn * 32 + nt * 8 + 2 * t;
        float bx = __ldg(bias + c);
        float by = __ldg(bias + c + 1);
        #pragma unroll
        for (int mt = 0; mt < 4; ++mt) {
            int r0 = rb + wm * 64 + mt * 16 + g;
            float2 lo, hi;
            lo.x = acc[mt][nt].x + bx;
            lo.y = acc[mt][nt].y + by;
            hi.x = acc[mt][nt].z + bx;
            hi.y = acc[mt][nt].w + by;
            if (RELU) {
                lo.x = fmaxf(lo.x, 0.f); lo.y = fmaxf(lo.y, 0.f);
                hi.x = fmaxf(hi.x, 0.f); hi.y = fmaxf(hi.y, 0.f);
            }
            if (r0 < M)     *(float2*)(out + (size_t)r0 * BN + c) = lo;
            if (r0 + 8 < M) *(float2*)(out + (size_t)(r0 + 8) * BN + c) = hi;
        }
    }
}

// ---------------- fp32 MLP for the 16-class head ---------------------------
template <int BM, int BN, int TM, int TN, bool RELU>
__global__ void mlp_kernel(const float* __restrict__ Z, const float* __restrict__ W,
                           const float* __restrict__ bias, float* __restrict__ out, int M) {
    constexpr int K = 128, KB = 32;
    constexpr int TX = BN / TN, TY = BM / TM, NT = TX * TY;
    __shared__ float As[BM][KB + 1];
    __shared__ float Ws[KB][BN];
    const int tid = threadIdx.x;
    const int tx = tid % TX, ty = tid / TX;
    const int rb = blockIdx.x * BM;

    float acc[TM][TN];
    #pragma unroll
    for (int i = 0; i < TM; ++i)
        #pragma unroll
        for (int j = 0; j < TN; ++j) acc[i][j] = 0.f;

    for (int kc = 0; kc < K; kc += KB) {
        #pragma unroll
        for (int idx = tid; idx < BM * (KB / 4); idx += NT) {
            int r = idx / (KB / 4);
            int f4 = idx % (KB / 4);
            float4 v = make_float4(0.f, 0.f, 0.f, 0.f);
            int gr = rb + r;
            if (gr < M) v = *(const float4*)(Z + (size_t)gr * K + kc + f4 * 4);
            As[r][f4 * 4 + 0] = v.x;
            As[r][f4 * 4 + 1] = v.y;
            As[r][f4 * 4 + 2] = v.z;
            As[r][f4 * 4 + 3] = v.w;
        }
        #pragma unroll
        for (int idx = tid; idx < KB * (BN / 4); idx += NT) {
            int kk = idx / (BN / 4);
            int c4 = idx % (BN / 4);
            *(float4*)&Ws[kk][c4 * 4] = *(const float4*)(W + (size_t)(kc + kk) * BN + c4 * 4);
        }
        __syncthreads();
        #pragma unroll
        for (int k = 0; k < KB; ++k) {
            float a[TM], bb[TN];
            #pragma unroll
            for (int i = 0; i < TM; ++i) a[i] = As[ty * TM + i][k];
            #pragma unroll
            for (int j = 0; j < TN; ++j) bb[j] = Ws[k][tx * TN + j];
            #pragma unroll
            for (int i = 0; i < TM; ++i)
                #pragma unroll
                for (int j = 0; j < TN; ++j)
                    acc[i][j] = fmaf(a[i], bb[j], acc[i][j]);
        }
        __syncthreads();
    }

    float bv[TN];
    #pragma unroll
    for (int j = 0; j < TN; ++j) bv[j] = __ldg(bias + tx * TN + j);
    #pragma unroll
    for (int i = 0; i < TM; ++i) {
        int gr = rb + ty * TM + i;
        if (gr < M) {
            #pragma unroll
            for (int j = 0; j < TN; ++j) {
                float o = acc[i][j] + bv[j];
                if (RELU) o = fmaxf(o, 0.f);
                out[(size_t)gr * BN + tx * TN + j] = o;
            }
        }
    }
}

// ---------------- host orchestration ----------------------------------------
extern "C" void kernel_launch(void* const* d_in, const int* in_sizes, int n_in,
                              void* d_out, int out_size) {
    (void)in_sizes; (void)n_in; (void)out_size;
    const float* feats = (const float*)d_in[0];
    const void*  srcv  = d_in[1];
    const void*  dstv  = d_in[2];
    const float* W0 = (const float*)d_in[3];
    const float* b0 = (const float*)d_in[4];
    const float* W1 = (const float*)d_in[5];
    const float* b1 = (const float*)d_in[6];
    const float* W2 = (const float*)d_in[7];
    const float* b2 = (const float*)d_in[8];
    const float* W3 = (const float*)d_in[9];
    const float* b3 = (const float*)d_in[10];
    const float* eps = (const float*)d_in[11];
    float* outp = (float*)d_out;

    void *p_src, *p_dst, *p_rank, *p_ssrc, *p_cnt, *p_row, *p_status, *p_inv, *p_wt, *p_z, *p_h;
    cudaGetSymbolAddress(&p_src, g_src);
    cudaGetSymbolAddress(&p_dst, g_dst);
    cudaGetSymbolAddress(&p_rank, g_rank);
    cudaGetSymbolAddress(&p_ssrc, g_ssrc);
    cudaGetSymbolAddress(&p_cnt, g_cnt);
    cudaGetSymbolAddress(&p_row, g_row);
    cudaGetSymbolAddress(&p_status, g_status);
    cudaGetSymbolAddress(&p_inv, g_inv);
    cudaGetSymbolAddress(&p_wt, g_wt);
    cudaGetSymbolAddress(&p_z, g_z);
    cudaGetSymbolAddress(&p_h, g_h);

    int* src32 = (int*)p_src;
    int* dst32 = (int*)p_dst;
    int* rankp = (int*)p_rank;
    int* ssrc  = (int*)p_ssrc;
    int* cnt   = (int*)p_cnt;
    int* rowp  = (int*)p_row;
    unsigned* statusp = (unsigned*)p_status;
    float* inv = (float*)p_inv;
    uint32_t* wt = (uint32_t*)p_wt;
    float* zb  = (float*)p_z;
    float* hb  = (float*)p_h;

    static bool attr_done = false;
    if (!attr_done) {
        cudaFuncSetAttribute(mma_mlp_kernel<true>,
                             cudaFuncAttributeMaxDynamicSharedMemorySize, MMA_SMEM_BYTES);
        attr_done = true;
    }

    const int EB = 256;
    const int egrid = (N_EDGES + EB - 1) / EB;

    // ---- preprocessing: 3 launches ----
    count_convert_kernel<<<egrid, EB>>>(srcv, dstv, W0, W1, W2,
                                        src32, dst32, rankp, cnt, wt);
    scan_kernel<<<NSCAN, 1024>>>(cnt, N_NODES, statusp, rowp, inv);
    scatter_kernel<<<egrid, EB>>>(src32, dst32, rankp, rowp, ssrc, statusp);

    // ---- 4 GIN layers (4th launch = aggz layer 0 -> ncu capture) ----------
    const int agrid = ((size_t)N_NODES * 32 + 255) / 256;
    const int mgrid = (N_NODES + 127) / 128;

    aggz_kernel<<<agrid, 256>>>(feats, rowp, ssrc, inv, eps, 0, zb);
    mma_mlp_kernel<true><<<mgrid, 256, MMA_SMEM_BYTES>>>(zb, wt, b0, hb, N_NODES);
    aggz_kernel<<<agrid, 256>>>(hb, rowp, ssrc, inv, eps, 1, zb);
    mma_mlp_kernel<true><<<mgrid, 256, MMA_SMEM_BYTES>>>(zb, wt + FEATS * FEATS, b1, hb, N_NODES);
    aggz_kernel<<<agrid, 256>>>(hb, rowp, ssrc, inv, eps, 2, zb);
    mma_mlp_kernel<true><<<mgrid, 256, MMA_SMEM_BYTES>>>(zb, wt + 2 * FEATS * FEATS, b2, hb, N_NODES);
    aggz_kernel<<<agrid, 256>>>(hb, rowp, ssrc, inv, eps, 3, zb);
    mlp_kernel<128, 16, 8, 2, false><<<mgrid, 128>>>(zb, W3, b3, outp, N_NODES);
}

// round 10
// speedup vs baseline: 1.6469x; 1.0963x over previous
#include <cuda_runtime.h>
#include <cuda_bf16.h>
#include <cstdint>

#define N_NODES 100000
#define N_EDGES 1600000
#define FEATS   128
#define N_CLASSES 16
#define NSCAN   98          // ceil(N_NODES / 1024)

// ---------------- static device scratch (no allocs allowed) ----------------
__device__ int      g_src[N_EDGES];
__device__ int      g_dst[N_EDGES];
__device__ int      g_rank[N_EDGES];       // rank of edge within its dst bucket
__device__ int      g_ssrc[N_EDGES];       // src*FEATS sorted by dst (CSR)
__device__ int      g_cnt[N_NODES];        // in-degree (self-cleaning)
__device__ int      g_row[N_NODES + 1];
__device__ unsigned g_status[NSCAN];       // lookback status (self-cleaning)
__device__ float    g_inv[N_NODES];
__device__ uint32_t g_wt[3 * FEATS * FEATS];  // W0..W2 pre-converted to tf32
__device__ float    g_z[(size_t)(N_NODES + 128) * FEATS];  // +128 pad rows
__device__ float    g_h[(size_t)N_NODES * FEATS];
__device__ __nv_bfloat16 g_hb[(size_t)N_NODES * FEATS];    // bf16 gather table

// ---------------- helpers ---------------------------------------------------
__device__ __forceinline__ uint32_t f2tf32(float f) {
    uint32_t u;
    asm("cvt.rna.tf32.f32 %0, %1;" : "=r"(u) : "f"(f));
    return u;
}

__device__ __forceinline__ void mma_tf32(float4& d, const uint32_t a[4], const uint32_t b[2]) {
    asm volatile(
        "mma.sync.aligned.m16n8k8.row.col.f32.tf32.tf32.f32 "
        "{%0,%1,%2,%3},{%4,%5,%6,%7},{%8,%9},{%0,%1,%2,%3};"
        : "+f"(d.x), "+f"(d.y), "+f"(d.z), "+f"(d.w)
        : "r"(a[0]), "r"(a[1]), "r"(a[2]), "r"(a[3]), "r"(b[0]), "r"(b[1]));
}

__device__ __forceinline__ void cp16(void* smem_dst, const void* gsrc) {
    uint32_t a = (uint32_t)__cvta_generic_to_shared(smem_dst);
    asm volatile("cp.async.cg.shared.global [%0], [%1], 16;\n" :: "r"(a), "l"(gsrc));
}
__device__ __forceinline__ void cp_commit() {
    asm volatile("cp.async.commit_group;\n" ::);
}
template <int N>
__device__ __forceinline__ void cp_wait() {
    asm volatile("cp.async.wait_group %0;\n" :: "n"(N));
}

// unpack 4 bf16 (uint2) into two float2 and accumulate
__device__ __forceinline__ void acc_bf4(uint2 p, float& ax, float& ay, float& az, float& aw) {
    float2 a = __bfloat1622float2(*(const __nv_bfloat162*)&p.x);
    float2 b = __bfloat1622float2(*(const __nv_bfloat162*)&p.y);
    ax += a.x; ay += a.y; az += b.x; aw += b.y;
}

// ---- count + convert + rank, fused int64 detection + weight tf32 convert ---
__global__ void count_convert_kernel(const void* srcv, const void* dstv,
                                     const float* __restrict__ W0,
                                     const float* __restrict__ W1,
                                     const float* __restrict__ W2,
                                     int* __restrict__ s32, int* __restrict__ d32,
                                     int* __restrict__ rank, int* __restrict__ cnt,
                                     uint32_t* __restrict__ wt) {
    __shared__ int s_not64;
    const int lt = threadIdx.x;
    if (lt == 0) s_not64 = 0;
    __syncthreads();
    if (lt < 64) {
        int a = ((const int*)srcv)[2 * lt + 1];
        int b = ((const int*)dstv)[2 * lt + 1];
        if ((a | b) != 0) atomicOr(&s_not64, 1);
    }
    __syncthreads();
    const bool is64 = (s_not64 == 0);

    int i = blockIdx.x * blockDim.x + lt;

    if (i < 3 * FEATS * FEATS) {
        const float* Wp = (i < FEATS * FEATS) ? W0
                        : (i < 2 * FEATS * FEATS) ? W1 : W2;
        wt[i] = f2tf32(Wp[i & (FEATS * FEATS - 1)]);
    }

    if (i >= N_EDGES) return;
    int s, d;
    if (is64) {
        s = (int)((const long long*)srcv)[i];
        d = (int)((const long long*)dstv)[i];
    } else {
        s = ((const int*)srcv)[i];
        d = ((const int*)dstv)[i];
    }
    s32[i] = s;
    d32[i] = d;
    rank[i] = atomicAdd(&cnt[d], 1);
}

// ---- single-pass scan with decoupled lookback ------------------------------
__global__ void scan_kernel(int* __restrict__ cnt, int n,
                            unsigned* __restrict__ status,
                            int* __restrict__ row, float* __restrict__ inv) {
    __shared__ int sm[2][1024];
    __shared__ int sred[32];
    __shared__ int s_agg, s_base;
    const int b = blockIdx.x, t = threadIdx.x;
    const int i = b * 1024 + t;
    const int x = (i < n) ? cnt[i] : 0;

    {
        int v = x;
        #pragma unroll
        for (int o = 16; o; o >>= 1) v += __shfl_down_sync(0xffffffffu, v, o);
        if ((t & 31) == 0) sred[t >> 5] = v;
        __syncthreads();
        if (t < 32) {
            int w = sred[t];
            #pragma unroll
            for (int o = 16; o; o >>= 1) w += __shfl_down_sync(0xffffffffu, w, o);
            if (t == 0) {
                s_agg = w;
                unsigned val = (b == 0) ? ((2u << 30) | (unsigned)w)
                                        : ((1u << 30) | (unsigned)w);
                atomicExch(&status[b], val);
            }
        }
    }
    __syncthreads();

    int pi = 0;
    sm[0][t] = x;
    __syncthreads();
    for (int o = 1; o < 1024; o <<= 1) {
        sm[1 - pi][t] = sm[pi][t] + ((t >= o) ? sm[pi][t - o] : 0);
        pi ^= 1;
        __syncthreads();
    }

    if (t < 32) {
        int base = 0;
        if (b > 0) {
            int j = b - 1;
            for (;;) {
                int idx = j - t;
                unsigned s = 0;
                if (idx >= 0) {
                    do { s = *(volatile unsigned*)&status[idx]; } while (s == 0);
                }
                unsigned pfx = __ballot_sync(0xffffffffu, (s >> 30) == 2u);
                if (pfx) {
                    int fl = __ffs(pfx) - 1;
                    int contrib = (t <= fl) ? (int)(s & 0x3FFFFFFFu) : 0;
                    #pragma unroll
                    for (int o = 16; o; o >>= 1) contrib += __shfl_down_sync(0xffffffffu, contrib, o);
                    base += __shfl_sync(0xffffffffu, contrib, 0);
                    break;
                } else {
                    int contrib = (idx >= 0) ? (int)(s & 0x3FFFFFFFu) : 0;
                    #pragma unroll
                    for (int o = 16; o; o >>= 1) contrib += __shfl_down_sync(0xffffffffu, contrib, o);
                    base += __shfl_sync(0xffffffffu, contrib, 0);
                    j -= 32;
                    if (j < 0) break;
                }
            }
            if (t == 0) atomicExch(&status[b], (2u << 30) | (unsigned)(base + s_agg));
        }
        if (t == 0) s_base = base;
    }
    __syncthreads();

    if (i < n) {
        int excl = sm[pi][t] - x + s_base;
        row[i] = excl;
        inv[i] = 1.0f / fmaxf((float)x, 1.0f);
        cnt[i] = 0;                       // self-clean for next replay
        if (i == n - 1) row[n] = excl + x;
    }
}

// ---- CSR scatter + feats->bf16 convert + status clean ----------------------
// Exactly N_EDGES threads; N_NODES*FEATS/8 == N_EDGES, so thread i also
// converts feats[8i .. 8i+8) into the bf16 gather table.
__global__ void scatter_kernel(const int* __restrict__ s32, const int* __restrict__ d32,
                               const int* __restrict__ rank, const int* __restrict__ row,
                               int* __restrict__ ssrc, unsigned* __restrict__ status,
                               const float* __restrict__ feats,
                               __nv_bfloat16* __restrict__ hbf) {
    int i = blockIdx.x * blockDim.x + threadIdx.x;
    if (i < NSCAN) status[i] = 0;
    if (i >= N_EDGES) return;

    // feats -> bf16 table (8 elems per thread, 32B read, 16B write)
    {
        float4 a = __ldg((const float4*)(feats + (size_t)i * 8));
        float4 b = __ldg((const float4*)(feats + (size_t)i * 8 + 4));
        __nv_bfloat162 p0 = __floats2bfloat162_rn(a.x, a.y);
        __nv_bfloat162 p1 = __floats2bfloat162_rn(a.z, a.w);
        __nv_bfloat162 p2 = __floats2bfloat162_rn(b.x, b.y);
        __nv_bfloat162 p3 = __floats2bfloat162_rn(b.z, b.w);
        uint4 pk;
        pk.x = *(uint32_t*)&p0; pk.y = *(uint32_t*)&p1;
        pk.z = *(uint32_t*)&p2; pk.w = *(uint32_t*)&p3;
        *(uint4*)(hbf + (size_t)i * 8) = pk;
    }

    int pos = row[d32[i]] + rank[i];
    ssrc[pos] = s32[i] * FEATS;
}

// ---- aggregation: z = (1+eps)*h_f32 + inv_deg * sum(bf16 neighbors) --------
// One warp per node, lane L handles features [4L, 4L+4).
__global__ void aggz_kernel(const float* __restrict__ h,
                            const __nv_bfloat16* __restrict__ hb,
                            const int* __restrict__ row, const int* __restrict__ ssrc,
                            const float* __restrict__ inv,
                            const float* __restrict__ eps, int layer,
                            float* __restrict__ z) {
    int gt = blockIdx.x * blockDim.x + threadIdx.x;
    int node = gt >> 5;
    if (node >= N_NODES) return;
    int lane = gt & 31;
    const int beg = __ldg(row + node);
    const int end = __ldg(row + node + 1);
    const int fo = lane * 4;

    float ax = 0.f, ay = 0.f, az = 0.f, aw = 0.f;
    int e = beg;
    for (; e + 3 < end; e += 4) {
        int o0 = __ldg(ssrc + e);
        int o1 = __ldg(ssrc + e + 1);
        int o2 = __ldg(ssrc + e + 2);
        int o3 = __ldg(ssrc + e + 3);
        uint2 p0 = __ldg((const uint2*)(hb + (size_t)o0 + fo));
        uint2 p1 = __ldg((const uint2*)(hb + (size_t)o1 + fo));
        uint2 p2 = __ldg((const uint2*)(hb + (size_t)o2 + fo));
        uint2 p3 = __ldg((const uint2*)(hb + (size_t)o3 + fo));
        acc_bf4(p0, ax, ay, az, aw);
        acc_bf4(p1, ax, ay, az, aw);
        acc_bf4(p2, ax, ay, az, aw);
        acc_bf4(p3, ax, ay, az, aw);
    }
    for (; e < end; ++e) {
        int o0 = __ldg(ssrc + e);
        uint2 p0 = __ldg((const uint2*)(hb + (size_t)o0 + fo));
        acc_bf4(p0, ax, ay, az, aw);
    }

    float sc = __ldg(inv + node);
    float e1 = 1.0f + __ldg(eps + layer);
    float4 hv = __ldg((const float4*)(h + (size_t)node * FEATS + fo));
    float4 zv;
    zv.x = e1 * hv.x + sc * ax;
    zv.y = e1 * hv.y + sc * ay;
    zv.z = e1 * hv.z + sc * az;
    zv.w = e1 * hv.w + sc * aw;
    *(float4*)(z + (size_t)node * FEATS + fo) = zv;
}

// ------- TF32 MLP, cp.async double-buffered: out = relu(Z @ W + b) ----------
// WRITE_BF: also emit bf16 copy for the next layer's gather table.
#define AS_STRIDE 36
#define WS_STRIDE 132
#define MMA_SMEM_BYTES (2 * 128 * AS_STRIDE * 4 + 2 * 32 * WS_STRIDE * 4)

template <bool RELU, bool WRITE_BF>
__global__ __launch_bounds__(256, 2)
void mma_mlp_kernel(const float* __restrict__ Z, const uint32_t* __restrict__ Wt,
                    const float* __restrict__ bias, float* __restrict__ out,
                    __nv_bfloat16* __restrict__ outb, int M) {
    constexpr int K = 128, KB = 32, BM = 128, BN = 128;
    extern __shared__ char smem_raw[];
    float*    As = (float*)smem_raw;                                 // [2][128][36]
    uint32_t* Ws = (uint32_t*)(smem_raw + 2 * BM * AS_STRIDE * 4);   // [2][32][132]

    const int tid = threadIdx.x;
    const int wid = tid >> 5;
    const int lane = tid & 31;
    const int g = lane >> 2;
    const int t = lane & 3;
    const int wm = wid >> 2;
    const int wn = wid & 3;
    const int rb = blockIdx.x * BM;

    auto load_tiles = [&](int st, int kc) {
        #pragma unroll
        for (int idx = tid; idx < BM * (KB / 4); idx += 256) {
            int r = idx >> 3, c4 = (idx & 7) * 4;
            cp16(&As[(st * BM + r) * AS_STRIDE + c4],
                 Z + (size_t)(rb + r) * K + kc + c4);
        }
        #pragma unroll
        for (int idx = tid; idx < KB * (BN / 4); idx += 256) {
            int k = idx >> 5, n4 = (idx & 31) * 4;
            cp16(&Ws[(st * KB + k) * WS_STRIDE + n4],
                 Wt + (size_t)(kc + k) * BN + n4);
        }
    };

    float4 acc[4][4];
    #pragma unroll
    for (int i = 0; i < 4; ++i)
        #pragma unroll
        for (int j = 0; j < 4; ++j) acc[i][j] = make_float4(0.f, 0.f, 0.f, 0.f);

    load_tiles(0, 0);
    cp_commit();

    #pragma unroll
    for (int kci = 0; kci < K / KB; ++kci) {
        if (kci < K / KB - 1) {
            load_tiles((kci + 1) & 1, (kci + 1) * KB);
            cp_commit();
            cp_wait<1>();
        } else {
            cp_wait<0>();
        }
        __syncthreads();
        const int st = kci & 1;

        #pragma unroll
        for (int ks = 0; ks < KB / 8; ++ks) {
            const int kb = ks * 8;
            uint32_t a[4][4], b[4][2];
            #pragma unroll
            for (int mt = 0; mt < 4; ++mt) {
                int r0 = wm * 64 + mt * 16 + g;
                a[mt][0] = f2tf32(As[(st * BM + r0) * AS_STRIDE + kb + t]);
                a[mt][1] = f2tf32(As[(st * BM + r0 + 8) * AS_STRIDE + kb + t]);
                a[mt][2] = f2tf32(As[(st * BM + r0) * AS_STRIDE + kb + t + 4]);
                a[mt][3] = f2tf32(As[(st * BM + r0 + 8) * AS_STRIDE + kb + t + 4]);
            }
            #pragma unroll
            for (int nt = 0; nt < 4; ++nt) {
                int c = wn * 32 + nt * 8 + g;
                b[nt][0] = Ws[(st * KB + kb + t) * WS_STRIDE + c];
                b[nt][1] = Ws[(st * KB + kb + t + 4) * WS_STRIDE + c];
            }
            #pragma unroll
            for (int mt = 0; mt < 4; ++mt)
                #pragma unroll
                for (int nt = 0; nt < 4; ++nt)
                    mma_tf32(acc[mt][nt], a[mt], b[nt]);
        }
        __syncthreads();
    }

    #pragma unroll
    for (int nt = 0; nt < 4; ++nt) {
        int c = wn * 32 + nt * 8 + 2 * t;
        float bx = __ldg(bias + c);
        float by = __ldg(bias + c + 1);
        #pragma unroll
        for (int mt = 0; mt < 4; ++mt) {
            int r0 = rb + wm * 64 + mt * 16 + g;
            float2 lo, hi;
            lo.x = acc[mt][nt].x + bx;
            lo.y = acc[mt][nt].y + by;
            hi.x = acc[mt][nt].z + bx;
            hi.y = acc[mt][nt].w + by;
            if (RELU) {
                lo.x = fmaxf(lo.x, 0.f); lo.y = fmaxf(lo.y, 0.f);
                hi.x = fmaxf(hi.x, 0.f); hi.y = fmaxf(hi.y, 0.f);
            }
            if (r0 < M) {
                *(float2*)(out + (size_t)r0 * BN + c) = lo;
                if (WRITE_BF) {
                    __nv_bfloat162 p = __floats2bfloat162_rn(lo.x, lo.y);
                    *(__nv_bfloat162*)(outb + (size_t)r0 * BN + c) = p;
                }
            }
            if (r0 + 8 < M) {
                *(float2*)(out + (size_t)(r0 + 8) * BN + c) = hi;
                if (WRITE_BF) {
                    __nv_bfloat162 p = __floats2bfloat162_rn(hi.x, hi.y);
                    *(__nv_bfloat162*)(outb + (size_t)(r0 + 8) * BN + c) = p;
                }
            }
        }
    }
}

// ---------------- fp32 MLP for the 16-class head ---------------------------
template <int BM, int BN, int TM, int TN, bool RELU>
__global__ void mlp_kernel(const float* __restrict__ Z, const float* __restrict__ W,
                           const float* __restrict__ bias, float* __restrict__ out, int M) {
    constexpr int K = 128, KB = 32;
    constexpr int TX = BN / TN, TY = BM / TM, NT = TX * TY;
    __shared__ float As[BM][KB + 1];
    __shared__ float Ws[KB][BN];
    const int tid = threadIdx.x;
    const int tx = tid % TX, ty = tid / TX;
    const int rb = blockIdx.x * BM;

    float acc[TM][TN];
    #pragma unroll
    for (int i = 0; i < TM; ++i)
        #pragma unroll
        for (int j = 0; j < TN; ++j) acc[i][j] = 0.f;

    for (int kc = 0; kc < K; kc += KB) {
        #pragma unroll
        for (int idx = tid; idx < BM * (KB / 4); idx += NT) {
            int r = idx / (KB / 4);
            int f4 = idx % (KB / 4);
            float4 v = make_float4(0.f, 0.f, 0.f, 0.f);
            int gr = rb + r;
            if (gr < M) v = *(const float4*)(Z + (size_t)gr * K + kc + f4 * 4);
            As[r][f4 * 4 + 0] = v.x;
            As[r][f4 * 4 + 1] = v.y;
            As[r][f4 * 4 + 2] = v.z;
            As[r][f4 * 4 + 3] = v.w;
        }
        #pragma unroll
        for (int idx = tid; idx < KB * (BN / 4); idx += NT) {
            int kk = idx / (BN / 4);
            int c4 = idx % (BN / 4);
            *(float4*)&Ws[kk][c4 * 4] = *(const float4*)(W + (size_t)(kc + kk) * BN + c4 * 4);
        }
        __syncthreads();
        #pragma unroll
        for (int k = 0; k < KB; ++k) {
            float a[TM], bb[TN];
            #pragma unroll
            for (int i = 0; i < TM; ++i) a[i] = As[ty * TM + i][k];
            #pragma unroll
            for (int j = 0; j < TN; ++j) bb[j] = Ws[k][tx * TN + j];
            #pragma unroll
            for (int i = 0; i < TM; ++i)
                #pragma unroll
                for (int j = 0; j < TN; ++j)
                    acc[i][j] = fmaf(a[i], bb[j], acc[i][j]);
        }
        __syncthreads();
    }

    float bv[TN];
    #pragma unroll
    for (int j = 0; j < TN; ++j) bv[j] = __ldg(bias + tx * TN + j);
    #pragma unroll
    for (int i = 0; i < TM; ++i) {
        int gr = rb + ty * TM + i;
        if (gr < M) {
            #pragma unroll
            for (int j = 0; j < TN; ++j) {
                float o = acc[i][j] + bv[j];
                if (RELU) o = fmaxf(o, 0.f);
                out[(size_t)gr * BN + tx * TN + j] = o;
            }
        }
    }
}

// ---------------- host orchestration ----------------------------------------
extern "C" void kernel_launch(void* const* d_in, const int* in_sizes, int n_in,
                              void* d_out, int out_size) {
    (void)in_sizes; (void)n_in; (void)out_size;
    const float* feats = (const float*)d_in[0];
    const void*  srcv  = d_in[1];
    const void*  dstv  = d_in[2];
    const float* W0 = (const float*)d_in[3];
    const float* b0 = (const float*)d_in[4];
    const float* W1 = (const float*)d_in[5];
    const float* b1 = (const float*)d_in[6];
    const float* W2 = (const float*)d_in[7];
    const float* b2 = (const float*)d_in[8];
    const float* W3 = (const float*)d_in[9];
    const float* b3 = (const float*)d_in[10];
    const float* eps = (const float*)d_in[11];
    float* outp = (float*)d_out;

    void *p_src, *p_dst, *p_rank, *p_ssrc, *p_cnt, *p_row, *p_status, *p_inv,
         *p_wt, *p_z, *p_h, *p_hb;
    cudaGetSymbolAddress(&p_src, g_src);
    cudaGetSymbolAddress(&p_dst, g_dst);
    cudaGetSymbolAddress(&p_rank, g_rank);
    cudaGetSymbolAddress(&p_ssrc, g_ssrc);
    cudaGetSymbolAddress(&p_cnt, g_cnt);
    cudaGetSymbolAddress(&p_row, g_row);
    cudaGetSymbolAddress(&p_status, g_status);
    cudaGetSymbolAddress(&p_inv, g_inv);
    cudaGetSymbolAddress(&p_wt, g_wt);
    cudaGetSymbolAddress(&p_z, g_z);
    cudaGetSymbolAddress(&p_h, g_h);
    cudaGetSymbolAddress(&p_hb, g_hb);

    int* src32 = (int*)p_src;
    int* dst32 = (int*)p_dst;
    int* rankp = (int*)p_rank;
    int* ssrc  = (int*)p_ssrc;
    int* cnt   = (int*)p_cnt;
    int* rowp  = (int*)p_row;
    unsigned* statusp = (unsigned*)p_status;
    float* inv = (float*)p_inv;
    uint32_t* wt = (uint32_t*)p_wt;
    float* zb  = (float*)p_z;
    float* hb  = (float*)p_h;
    __nv_bfloat16* hbf = (__nv_bfloat16*)p_hb;

    static bool attr_done = false;
    if (!attr_done) {
        cudaFuncSetAttribute(mma_mlp_kernel<true, true>,
                             cudaFuncAttributeMaxDynamicSharedMemorySize, MMA_SMEM_BYTES);
        attr_done = true;
    }

    const int EB = 256;
    const int egrid = (N_EDGES + EB - 1) / EB;

    // ---- preprocessing: 3 launches ----
    count_convert_kernel<<<egrid, EB>>>(srcv, dstv, W0, W1, W2,
                                        src32, dst32, rankp, cnt, wt);
    scan_kernel<<<NSCAN, 1024>>>(cnt, N_NODES, statusp, rowp, inv);
    scatter_kernel<<<egrid, EB>>>(src32, dst32, rankp, rowp, ssrc, statusp,
                                  feats, hbf);

    // ---- 4 GIN layers (4th launch = aggz layer 0 -> ncu capture) ----------
    const int agrid = ((size_t)N_NODES * 32 + 255) / 256;
    const int mgrid = (N_NODES + 127) / 128;

    aggz_kernel<<<agrid, 256>>>(feats, hbf, rowp, ssrc, inv, eps, 0, zb);
    mma_mlp_kernel<true, true><<<mgrid, 256, MMA_SMEM_BYTES>>>(zb, wt, b0, hb, hbf, N_NODES);
    aggz_kernel<<<agrid, 256>>>(hb, hbf, rowp, ssrc, inv, eps, 1, zb);
    mma_mlp_kernel<true, true><<<mgrid, 256, MMA_SMEM_BYTES>>>(zb, wt + FEATS * FEATS, b1, hb, hbf, N_NODES);
    aggz_kernel<<<agrid, 256>>>(hb, hbf, rowp, ssrc, inv, eps, 2, zb);
    mma_mlp_kernel<true, true><<<mgrid, 256, MMA_SMEM_BYTES>>>(zb, wt + 2 * FEATS * FEATS, b2, hb, hbf, N_NODES);
    aggz_kernel<<<agrid, 256>>>(hb, hbf, rowp, ssrc, inv, eps, 3, zb);
    mlp_kernel<128, 16, 8, 2, false><<<mgrid, 128>>>(zb, W3, b3, outp, N_NODES);
}